// round 14
// baseline (speedup 1.0000x reference)
#include <cuda_runtime.h>
#include <cuda_fp16.h>
#include <cstdint>

#define B_   64
#define T_   512
#define H_   1024
#define L_   4
#define O_   256
#define NCTA 128
#define NTHR 256
#define NBUF 8                             // h ring depth (steps of cross-layer skew)

#define KC      256                        // K per chunk
#define NCHUNK  8                          // 2048 / 256
#define WSTG    65536                      // W tile 128 rows x 512B (pre-swizzled, bulk)
#define ASTG    32768                      // A tile  64 rows x 512B
#define STG     (WSTG + ASTG)              // 98304 per stage
#define OFF_MBAR (2 * STG)                 // 196608 : two mbarriers
#define SMEM_TOTAL (OFF_MBAR + 64)         // 196672

#define WCHUNK_HALFS 32768                 // 64KB per W chunk

// ---------------- scratch (static device globals; no allocation) ----------------
// W pre-swizzled contiguous chunks: [l*32+s][kc=8][32768 halfs]
__device__ __half g_Wc[(size_t)NCTA * NCHUNK * WCHUNK_HALFS];
__device__ __half g_x[(size_t)T_ * B_ * H_];           // x fp16, [t][b][d]
__device__ __half g_h[(size_t)NBUF * L_ * B_ * H_];    // h ring, [slot][l][b][h]
__device__ float  g_bias[L_ * 4 * H_];                 // bih + bhh
__device__ float  g_h3[B_ * H_];                       // final layer-3 h (fp32)
__device__ unsigned g_done[L_];                        // per-layer step counters (32/step)
__device__ unsigned g_barGen;
__device__ unsigned g_barCnt;

// ---------------- helpers --------------------------------------------------------
__device__ __forceinline__ uint32_t smem_u32(const void* p) {
    uint32_t a;
    asm("{ .reg .u64 t; cvta.to.shared.u64 t, %1; cvt.u32.u64 %0, t; }" : "=r"(a) : "l"(p));
    return a;
}
__device__ __forceinline__ void cpa16(uint32_t dst, const void* src) {
    asm volatile("cp.async.cg.shared.global [%0], [%1], 16;" :: "r"(dst), "l"(src) : "memory");
}
__device__ __forceinline__ void cp_commit() {
    asm volatile("cp.async.commit_group;" ::: "memory");
}
__device__ __forceinline__ void cp_wait0() {
    asm volatile("cp.async.wait_group 0;" ::: "memory");
}
__device__ __forceinline__ void mbar_init(uint32_t mb) {
    asm volatile("mbarrier.init.shared.b64 [%0], %1;" :: "r"(mb), "r"(1u) : "memory");
}
__device__ __forceinline__ void mbar_wait(uint32_t mb, unsigned parity) {
    asm volatile(
        "{\n\t.reg .pred P;\n\t"
        "W_%=:\n\t"
        "mbarrier.try_wait.parity.acquire.cta.shared::cta.b64 P, [%0], %1, 0x989680;\n\t"
        "@P bra.uni D_%=;\n\t"
        "bra.uni W_%=;\n\t"
        "D_%=:\n\t}"
        :: "r"(mb), "r"(parity) : "memory");
}
__device__ __forceinline__ void bulkW(uint32_t dst, const void* src, uint32_t mb) {
    asm volatile("mbarrier.arrive.expect_tx.shared.b64 _, [%0], %1;"
                 :: "r"(mb), "r"(65536u) : "memory");
    asm volatile("cp.async.bulk.shared::cta.global.mbarrier::complete_tx::bytes "
                 "[%0], [%1], %2, [%3];"
                 :: "r"(dst), "l"(src), "r"(65536u), "r"(mb) : "memory");
}
__device__ __forceinline__ void ldsm4(uint32_t* r, uint32_t a) {
    asm volatile("ldmatrix.sync.aligned.m8n8.x4.shared.b16 {%0,%1,%2,%3}, [%4];"
                 : "=r"(r[0]), "=r"(r[1]), "=r"(r[2]), "=r"(r[3]) : "r"(a));
}
__device__ __forceinline__ void mma16816(float* c, const uint32_t* a, uint32_t b0, uint32_t b1) {
    asm volatile(
        "mma.sync.aligned.m16n8k16.row.col.f32.f16.f16.f32 "
        "{%0,%1,%2,%3}, {%4,%5,%6,%7}, {%8,%9}, {%0,%1,%2,%3};\n"
        : "+f"(c[0]), "+f"(c[1]), "+f"(c[2]), "+f"(c[3])
        : "r"(a[0]), "r"(a[1]), "r"(a[2]), "r"(a[3]), "r"(b0), "r"(b1));
}
__device__ __forceinline__ float tanh_fast(float x) {
    float y;
    asm("tanh.approx.f32 %0, %1;" : "=f"(y) : "f"(x));
    return y;
}
__device__ __forceinline__ float sig_fast(float x) {
    return 0.5f * tanh_fast(0.5f * x) + 0.5f;
}

// ---------------- startup grid barrier (replay-safe, used once) ------------------
__device__ __forceinline__ void gridBarrier() {
    __threadfence();
    __syncthreads();
    if (threadIdx.x == 0) {
        unsigned gen = *((volatile unsigned*)&g_barGen);
        __threadfence();
        unsigned prev = atomicAdd(&g_barCnt, 1u);
        if (prev == NCTA - 1) {
            g_barCnt = 0;
            __threadfence();
            atomicAdd(&g_barGen, 1u);
        } else {
            while (*((volatile unsigned*)&g_barGen) == gen) { }
        }
    }
    __syncthreads();
}
__device__ __forceinline__ void waitGE(const unsigned* p, unsigned v) {
    while (*((volatile const unsigned*)p) < v) { }
}

// ---------------- prep: pre-swizzled contiguous W chunks + x fp16 + bias ---------
__global__ void prep_kernel(const float* __restrict__ x,
                            const float* __restrict__ Wih,
                            const float* __restrict__ Whh,
                            const float* __restrict__ bih,
                            const float* __restrict__ bhh) {
    long long tid = (long long)blockIdx.x * blockDim.x + threadIdx.x;
    long long stride = (long long)gridDim.x * blockDim.x;

    const long long NW = (long long)NCTA * NCHUNK * WCHUNK_HALFS;  // 33,554,432
    for (long long n = tid; n < NW; n += stride) {
        int pos = (int)(n & (WCHUNK_HALFS - 1));
        int kc  = (int)((n >> 15) & 7);
        int ls  = (int)(n >> 18);
        int l = ls >> 5, s = ls & 31;
        int j  = pos >> 8;                 // tile row 0..127 (= gate*32 + col)
        int hp = pos & 255;
        int u  = hp >> 3;                  // stored 16B slot
        int e8 = hp & 7;
        int c  = u ^ (j & 7);              // original 16B column (swizzle inverse)
        int k  = kc * 256 + c * 8 + e8;
        int g = j >> 5, jj = j & 31;
        int row = g * 1024 + s * 32 + jj;
        float v = (k < 1024)
            ? Wih[((long long)l * 4096 + row) * 1024 + k]
            : Whh[((long long)l * 4096 + row) * 1024 + (k - 1024)];
        g_Wc[n] = __float2half_rn(v);
    }

    const long long NX = (long long)T_ * B_ * H_;
    for (long long n = tid; n < NX; n += stride) {
        int d = (int)(n & 1023);
        int b = (int)((n >> 10) & 63);
        int t = (int)(n >> 16);
        g_x[n] = __float2half_rn(x[((long long)b * T_ + t) * H_ + d]);
    }

    for (long long n = tid; n < L_ * 4 * H_; n += stride)
        g_bias[n] = bih[n] + bhh[n];
}

// ---------------- persistent LSTM kernel (dataflow-synced, register cell) --------
__global__ void __launch_bounds__(NTHR, 1) lstm_kernel() {
    extern __shared__ __align__(1024) char smem[];
    const uint32_t sb = smem_u32(smem);
    const int tid = threadIdx.x;
    const int lane = tid & 31;
    const int wid = tid >> 5;
    const int bid = blockIdx.x;
    const int l = bid >> 5;          // layer
    const int s = bid & 31;          // gate-column slice (32 h cols)

    const uint32_t mb0 = sb + OFF_MBAR;
    const uint32_t mb1 = sb + OFF_MBAR + 8;

    if (tid == 0) { mbar_init(mb0); mbar_init(mb1); }
    if (bid == 0 && tid < L_) g_done[tid] = 0u;
    {
        const int total = (NBUF * L_ * B_ * H_) / 8;   // uint4 count
        uint4 z = make_uint4(0, 0, 0, 0);
        for (int i = bid * NTHR + tid; i < total; i += NCTA * NTHR)
            ((uint4*)g_h)[i] = z;
    }
    __syncthreads();

    // warp / lane tiling: wm = batch half; wn = hc-octet; warp's 4 n-tiles = 4 gates
    const int wm = wid >> 2;
    const int wn = wid & 3;
    const int t8 = lane >> 3;
    const int r8 = lane & 7;
    const int grp = lane >> 2;
    const int tg = lane & 3;
    const uint32_t swz = (uint32_t)r8;
    const uint32_t tA = (uint32_t)(t8 >> 1);
    const uint32_t tB = (uint32_t)(t8 & 1);

    // per-thread bias (4 gates x 2 cols) + register-resident cell state
    float bias_r[4][2];
    #pragma unroll
    for (int g = 0; g < 4; ++g)
        #pragma unroll
        for (int e = 0; e < 2; ++e)
            bias_r[g][e] = g_bias[l * 4096 + g * 1024 + s * 32 + wn * 8 + tg * 2 + e];
    float cst[2][2][2];
    #pragma unroll
    for (int mi = 0; mi < 2; ++mi)
        #pragma unroll
        for (int rh = 0; rh < 2; ++rh)
            cst[mi][rh][0] = cst[mi][rh][1] = 0.f;

    uint32_t aBase[2][2], bBase[2][2];
    #pragma unroll
    for (int st = 0; st < 2; ++st) {
        uint32_t wa = sb + st * STG;
        #pragma unroll
        for (int mi = 0; mi < 2; ++mi) {
            int m = wm * 32 + mi * 16 + (t8 & 1) * 8 + r8;
            aBase[st][mi] = wa + WSTG + m * 512;
        }
        #pragma unroll
        for (int p = 0; p < 2; ++p) {
            int j = ((t8 >> 1) + 2 * p) * 32 + wn * 8 + r8;   // gate rows
            bBase[st][p] = wa + j * 512;
        }
    }

    const __half* Wbase = g_Wc + (size_t)(l * 32 + s) * NCHUNK * WCHUNK_HALFS;

    // first-step W bulk prefetch, then startup barrier
    if (tid == 0) {
        bulkW(sb + 0 * STG, Wbase + 0 * WCHUNK_HALFS, mb0);
        bulkW(sb + 1 * STG, Wbase + 1 * WCHUNK_HALFS, mb1);
    }
    gridBarrier();

    unsigned ph[2] = {0u, 0u};

    for (int t = 0; t < T_; ++t) {
        // ---- dataflow waits ----
        if (tid == 0) {
            if (l > 0) waitGE(&g_done[l - 1], 32u * (unsigned)(t + 1));
            if (t > 0) waitGE(&g_done[l], 32u * (unsigned)t);
            if (l < 3 && t >= NBUF - 1)
                waitGE(&g_done[l + 1], 32u * (unsigned)(t - (NBUF - 1) + 1));
        }
        __syncthreads();
        __threadfence();

        const int slot  = t & (NBUF - 1);
        const int pslot = (t - 1) & (NBUF - 1);
        const __half* in  = (l == 0) ? (g_x + (size_t)t * (B_ * H_))
                                     : (g_h + ((size_t)slot * L_ + (l - 1)) * (B_ * H_));
        const __half* rec = g_h + ((size_t)pslot * L_ + l) * (B_ * H_);

        auto issueA = [&](int kc, int st) {
            const __half* Asrc = (kc < 4) ? in : rec;
            const int kloc = (kc & 3) * KC;
            uint32_t adst = sb + st * STG + WSTG;
            #pragma unroll
            for (int q = 0; q < 8; ++q) {
                int f = tid + q * 256;
                int b = f >> 5, c = f & 31;
                uint32_t d = adst + (uint32_t)(b * 512) + ((uint32_t)(c ^ (b & 7)) << 4);
                cpa16(d, Asrc + (size_t)b * 1024 + kloc + c * 8);
            }
        };

        float acc[2][4][4];
        #pragma unroll
        for (int mi = 0; mi < 2; ++mi)
            #pragma unroll
            for (int ni = 0; ni < 4; ++ni)
                #pragma unroll
                for (int q = 0; q < 4; ++q) acc[mi][ni][q] = 0.f;

        issueA(0, 0); cp_commit();

        #pragma unroll
        for (int kc = 0; kc < NCHUNK; ++kc) {
            const int st = kc & 1;
            cp_wait0();                              // A chunk kc (own issues)
            mbar_wait(st ? mb1 : mb0, ph[st]);       // W chunk kc (bulk)
            ph[st] ^= 1u;
            __syncthreads();                         // all warps ready; stage reusable
            if (kc + 1 < NCHUNK) {
                if (tid == 0 && kc + 1 >= 2)
                    bulkW(sb + ((kc + 1) & 1) * STG,
                          Wbase + (size_t)(kc + 1) * WCHUNK_HALFS,
                          ((kc + 1) & 1) ? mb1 : mb0);
                issueA(kc + 1, (kc + 1) & 1);
                cp_commit();
            }

            #pragma unroll
            for (int kk = 0; kk < 16; ++kk) {
                const uint32_t acol = (((uint32_t)(2 * kk) + tA) ^ swz) << 4;
                const uint32_t bcol = (((uint32_t)(2 * kk) + tB) ^ swz) << 4;
                uint32_t a[2][4], bf[2][4];
                ldsm4(a[0], aBase[st][0] + acol);
                ldsm4(a[1], aBase[st][1] + acol);
                ldsm4(bf[0], bBase[st][0] + bcol);   // gates 0,1
                ldsm4(bf[1], bBase[st][1] + bcol);   // gates 2,3
                #pragma unroll
                for (int mi = 0; mi < 2; ++mi) {
                    mma16816(acc[mi][0], a[mi], bf[0][0], bf[0][1]);
                    mma16816(acc[mi][1], a[mi], bf[0][2], bf[0][3]);
                    mma16816(acc[mi][2], a[mi], bf[1][0], bf[1][1]);
                    mma16816(acc[mi][3], a[mi], bf[1][2], bf[1][3]);
                }
            }
        }

        // ---- cell math fully in registers (acc[mi][gate][q], q = rh*2 + e) ----
        __half* hout = g_h + ((size_t)slot * L_ + l) * (B_ * H_);
        #pragma unroll
        for (int mi = 0; mi < 2; ++mi)
            #pragma unroll
            for (int rh = 0; rh < 2; ++rh) {
                float hv2[2];
                #pragma unroll
                for (int e = 0; e < 2; ++e) {
                    const int q = rh * 2 + e;
                    float ai = acc[mi][0][q] + bias_r[0][e];
                    float af = acc[mi][1][q] + bias_r[1][e];
                    float ag = acc[mi][2][q] + bias_r[2][e];
                    float ao = acc[mi][3][q] + bias_r[3][e];
                    float ig = sig_fast(ai);
                    float fg = sig_fast(af);
                    float gg = tanh_fast(ag);
                    float og = sig_fast(ao);
                    float cs = fg * cst[mi][rh][e] + ig * gg;
                    cst[mi][rh][e] = cs;
                    hv2[e] = og * tanh_fast(cs);
                }
                int b = wm * 32 + mi * 16 + rh * 8 + grp;
                int go = b * 1024 + s * 32 + wn * 8 + tg * 2;
                __half2 hp = __floats2half2_rn(hv2[0], hv2[1]);
                __stcg((unsigned*)(hout + go), *(unsigned*)&hp);
                if (l == 3 && t == T_ - 1) {
                    g_h3[go]     = hv2[0];
                    g_h3[go + 1] = hv2[1];
                }
            }
        __syncthreads();                 // all h writes of this CTA issued

        if (tid == 0) {
            __threadfence();             // release: h visible before count
            atomicAdd(&g_done[l], 1u);
            if (t + 1 < T_) {            // next-step W bulk prefetch
                bulkW(sb + 0 * STG, Wbase + 0 * WCHUNK_HALFS, mb0);
                bulkW(sb + 1 * STG, Wbase + 1 * WCHUNK_HALFS, mb1);
            }
        }
    }
}

// ---------------- final FC: out[b][o] = h3[b] . fc_w[o] + fc_b[o] ----------------
__global__ void fc_kernel(const float* __restrict__ fc_w,
                          const float* __restrict__ fc_b,
                          float* __restrict__ out) {
    __shared__ float hs[H_];
    const int b = blockIdx.x;
    const int o = threadIdx.x;
    for (int k = o; k < H_; k += O_) hs[k] = g_h3[b * H_ + k];
    __syncthreads();
    const float* w = fc_w + (long long)o * H_;
    float a0 = 0.f, a1 = 0.f, a2 = 0.f, a3 = 0.f;
    #pragma unroll 4
    for (int k = 0; k < H_; k += 4) {
        a0 += hs[k + 0] * __ldg(w + k + 0);
        a1 += hs[k + 1] * __ldg(w + k + 1);
        a2 += hs[k + 2] * __ldg(w + k + 2);
        a3 += hs[k + 3] * __ldg(w + k + 3);
    }
    out[b * O_ + o] = fc_b[o] + ((a0 + a1) + (a2 + a3));
}

// ---------------- launch ----------------------------------------------------------
extern "C" void kernel_launch(void* const* d_in, const int* in_sizes, int n_in,
                              void* d_out, int out_size) {
    (void)in_sizes; (void)n_in; (void)out_size;
    const float* x    = (const float*)d_in[0];
    const float* Wih  = (const float*)d_in[1];
    const float* Whh  = (const float*)d_in[2];
    const float* bih  = (const float*)d_in[3];
    const float* bhh  = (const float*)d_in[4];
    const float* fc_w = (const float*)d_in[5];
    const float* fc_b = (const float*)d_in[6];

    cudaFuncSetAttribute(lstm_kernel, cudaFuncAttributeMaxDynamicSharedMemorySize, SMEM_TOTAL);
    prep_kernel<<<2048, 256>>>(x, Wih, Whh, bih, bhh);
    lstm_kernel<<<NCTA, NTHR, SMEM_TOTAL>>>();
    fc_kernel<<<B_, O_>>>(fc_w, fc_b, (float*)d_out);
}

// round 15
// speedup vs baseline: 1.5226x; 1.5226x over previous
#include <cuda_runtime.h>
#include <cuda_fp16.h>
#include <cstdint>

#define B_   64
#define T_   512
#define H_   1024
#define L_   4
#define O_   256
#define NCTA 128
#define NTHR 256
#define NBUF 8                             // h ring depth (steps of cross-layer skew)

#define KC      256                        // K per chunk
#define NCHUNK  8                          // 2048 / 256
#define WSTG    65536                      // W tile 128 rows x 512B
#define ASTG    32768                      // A tile  64 rows x 512B
#define STG     (WSTG + ASTG)              // 98304 per stage
#define SMEM_TOTAL (2 * STG)               // 196608 — no sG/sC needed (register cell)

// ---------------- scratch (static device globals; no allocation) ----------------
__device__ __half g_Wc[(size_t)L_ * 32 * 128 * 2048];  // [l][s][j=128][k=2048] fp16
__device__ __half g_x[(size_t)T_ * B_ * H_];           // x fp16, [t][b][d]
__device__ __half g_h[(size_t)NBUF * L_ * B_ * H_];    // h ring, [slot][l][b][h]
__device__ float  g_bias[L_ * 4 * H_];                 // bih + bhh
__device__ float  g_h3[B_ * H_];                       // final layer-3 h (fp32)
__device__ unsigned g_done[L_];                        // per-layer step counters (32/step)
__device__ unsigned g_barGen;
__device__ unsigned g_barCnt;

// ---------------- helpers --------------------------------------------------------
__device__ __forceinline__ uint32_t smem_u32(const void* p) {
    uint32_t a;
    asm("{ .reg .u64 t; cvta.to.shared.u64 t, %1; cvt.u32.u64 %0, t; }" : "=r"(a) : "l"(p));
    return a;
}
__device__ __forceinline__ void cpa16(uint32_t dst, const void* src) {
    asm volatile("cp.async.cg.shared.global [%0], [%1], 16;" :: "r"(dst), "l"(src) : "memory");
}
__device__ __forceinline__ void cp_commit() {
    asm volatile("cp.async.commit_group;" ::: "memory");
}
__device__ __forceinline__ void cp_wait0() {
    asm volatile("cp.async.wait_group 0;" ::: "memory");
}
__device__ __forceinline__ void ldsm4(uint32_t* r, uint32_t a) {
    asm volatile("ldmatrix.sync.aligned.m8n8.x4.shared.b16 {%0,%1,%2,%3}, [%4];"
                 : "=r"(r[0]), "=r"(r[1]), "=r"(r[2]), "=r"(r[3]) : "r"(a));
}
__device__ __forceinline__ void mma16816(float* c, const uint32_t* a, uint32_t b0, uint32_t b1) {
    asm volatile(
        "mma.sync.aligned.m16n8k16.row.col.f32.f16.f16.f32 "
        "{%0,%1,%2,%3}, {%4,%5,%6,%7}, {%8,%9}, {%0,%1,%2,%3};\n"
        : "+f"(c[0]), "+f"(c[1]), "+f"(c[2]), "+f"(c[3])
        : "r"(a[0]), "r"(a[1]), "r"(a[2]), "r"(a[3]), "r"(b0), "r"(b1));
}
__device__ __forceinline__ float tanh_fast(float x) {
    float y;
    asm("tanh.approx.f32 %0, %1;" : "=f"(y) : "f"(x));
    return y;
}
__device__ __forceinline__ float sig_fast(float x) {
    return 0.5f * tanh_fast(0.5f * x) + 0.5f;
}

// ---------------- startup grid barrier (replay-safe, used once) ------------------
__device__ __forceinline__ void gridBarrier() {
    __threadfence();
    __syncthreads();
    if (threadIdx.x == 0) {
        unsigned gen = *((volatile unsigned*)&g_barGen);
        __threadfence();
        unsigned prev = atomicAdd(&g_barCnt, 1u);
        if (prev == NCTA - 1) {
            g_barCnt = 0;
            __threadfence();
            atomicAdd(&g_barGen, 1u);
        } else {
            while (*((volatile unsigned*)&g_barGen) == gen) { }
        }
    }
    __syncthreads();
}
__device__ __forceinline__ void waitGE(const unsigned* p, unsigned v) {
    while (*((volatile const unsigned*)p) < v) { }
}

// ---------------- prep: weight swizzle + x fp16 + fused bias ---------------------
__global__ void prep_kernel(const float* __restrict__ x,
                            const float* __restrict__ Wih,
                            const float* __restrict__ Whh,
                            const float* __restrict__ bih,
                            const float* __restrict__ bhh) {
    long long tid = (long long)blockIdx.x * blockDim.x + threadIdx.x;
    long long stride = (long long)gridDim.x * blockDim.x;

    const long long NW = (long long)L_ * 32 * 128 * 2048;
    for (long long n = tid; n < NW; n += stride) {
        int k = (int)(n & 2047);
        int j = (int)((n >> 11) & 127);
        int s = (int)((n >> 18) & 31);
        int l = (int)(n >> 23);
        int g = j >> 5, jj = j & 31;
        int row = g * 1024 + s * 32 + jj;
        float v = (k < 1024)
            ? Wih[((long long)l * 4096 + row) * 1024 + k]
            : Whh[((long long)l * 4096 + row) * 1024 + (k - 1024)];
        g_Wc[n] = __float2half_rn(v);
    }

    const long long NX = (long long)T_ * B_ * H_;
    for (long long n = tid; n < NX; n += stride) {
        int d = (int)(n & 1023);
        int b = (int)((n >> 10) & 63);
        int t = (int)(n >> 16);
        g_x[n] = __float2half_rn(x[((long long)b * T_ + t) * H_ + d]);
    }

    for (long long n = tid; n < L_ * 4 * H_; n += stride)
        g_bias[n] = bih[n] + bhh[n];
}

// ---------------- persistent LSTM kernel (dataflow-synced, register cell) --------
__global__ void __launch_bounds__(NTHR, 1) lstm_kernel() {
    extern __shared__ __align__(1024) char smem[];
    const uint32_t sb = smem_u32(smem);
    const int tid = threadIdx.x;
    const int lane = tid & 31;
    const int wid = tid >> 5;
    const int bid = blockIdx.x;
    const int l = bid >> 5;          // layer
    const int s = bid & 31;          // gate-column slice (32 h cols)

    // reset counters (CTA 0) + zero h ring, then one startup barrier
    if (bid == 0 && tid < L_) g_done[tid] = 0u;
    {
        const int total = (NBUF * L_ * B_ * H_) / 8;   // uint4 count
        uint4 z = make_uint4(0, 0, 0, 0);
        for (int i = bid * NTHR + tid; i < total; i += NCTA * NTHR)
            ((uint4*)g_h)[i] = z;
    }

    // warp / lane tiling: wm = batch half; wn = hc-octet; warp's 4 n-tiles = 4 gates
    const int wm = wid >> 2;
    const int wn = wid & 3;
    const int t8 = lane >> 3;
    const int r8 = lane & 7;
    const int grp = lane >> 2;
    const int tg = lane & 3;
    const uint32_t swz = (uint32_t)r8;
    const uint32_t tA = (uint32_t)(t8 >> 1);
    const uint32_t tB = (uint32_t)(t8 & 1);

    // per-thread bias (4 gates x 2 cols) + register-resident cell state
    float bias_r[4][2];
    #pragma unroll
    for (int g = 0; g < 4; ++g)
        #pragma unroll
        for (int e = 0; e < 2; ++e)
            bias_r[g][e] = g_bias[l * 4096 + g * 1024 + s * 32 + wn * 8 + tg * 2 + e];
    float cst[2][2][2];
    #pragma unroll
    for (int mi = 0; mi < 2; ++mi)
        #pragma unroll
        for (int rh = 0; rh < 2; ++rh)
            cst[mi][rh][0] = cst[mi][rh][1] = 0.f;

    uint32_t aBase[2][2], bBase[2][2];
    #pragma unroll
    for (int st = 0; st < 2; ++st) {
        uint32_t wa = sb + st * STG;
        #pragma unroll
        for (int mi = 0; mi < 2; ++mi) {
            int m = wm * 32 + mi * 16 + (t8 & 1) * 8 + r8;
            aBase[st][mi] = wa + WSTG + m * 512;
        }
        #pragma unroll
        for (int p = 0; p < 2; ++p) {
            int j = ((t8 >> 1) + 2 * p) * 32 + wn * 8 + r8;   // gate rows (p: gates 0/1, 2/3)
            bBase[st][p] = wa + j * 512;
        }
    }

    const __half* Wbase = g_Wc + (size_t)(l * 32 + s) * 128 * 2048;

    auto issueW = [&](int kc, int st) {
        const __half* Wsrc = Wbase + kc * KC;
        uint32_t wdst = sb + st * STG;
        #pragma unroll
        for (int q = 0; q < 16; ++q) {
            int f = tid + q * 256;
            int j = f >> 5, c = f & 31;
            uint32_t d = wdst + (uint32_t)(j * 512) + ((uint32_t)(c ^ (j & 7)) << 4);
            cpa16(d, Wsrc + (size_t)j * 2048 + c * 8);
        }
    };

    // first-step W prefetch (uncommitted), then startup barrier
    issueW(0, 0); issueW(1, 1);
    gridBarrier();

    for (int t = 0; t < T_; ++t) {
        // ---- dataflow waits (tid 0 spins, others park at the sync) ----
        if (tid == 0) {
            if (l > 0) waitGE(&g_done[l - 1], 32u * (unsigned)(t + 1)); // upstream h(t)
            if (t > 0) waitGE(&g_done[l], 32u * (unsigned)t);           // peers' h(t-1)
            if (l < 3 && t >= NBUF - 1)                                  // WAR on slot reuse
                waitGE(&g_done[l + 1], 32u * (unsigned)(t - (NBUF - 1) + 1));
        }
        __syncthreads();
        __threadfence();   // acquire

        const int slot  = t & (NBUF - 1);
        const int pslot = (t - 1) & (NBUF - 1);
        const __half* in  = (l == 0) ? (g_x + (size_t)t * (B_ * H_))
                                     : (g_h + ((size_t)slot * L_ + (l - 1)) * (B_ * H_));
        const __half* rec = g_h + ((size_t)pslot * L_ + l) * (B_ * H_);

        auto issueA = [&](int kc, int st) {
            const __half* Asrc = (kc < 4) ? in : rec;
            const int kloc = (kc & 3) * KC;
            uint32_t adst = sb + st * STG + WSTG;
            #pragma unroll
            for (int q = 0; q < 8; ++q) {
                int f = tid + q * 256;
                int b = f >> 5, c = f & 31;
                uint32_t d = adst + (uint32_t)(b * 512) + ((uint32_t)(c ^ (b & 7)) << 4);
                cpa16(d, Asrc + (size_t)b * 1024 + kloc + c * 8);
            }
        };

        float acc[2][4][4];
        #pragma unroll
        for (int mi = 0; mi < 2; ++mi)
            #pragma unroll
            for (int ni = 0; ni < 4; ++ni)
                #pragma unroll
                for (int q = 0; q < 4; ++q) acc[mi][ni][q] = 0.f;

        // W0/W1 already in flight (issued at end of previous step, uncommitted)
        issueA(0, 0); cp_commit();      // g0 = {W0, W1, A0}

        #pragma unroll
        for (int kc = 0; kc < NCHUNK; ++kc) {
            const int st = kc & 1;
            cp_wait0();
            __syncthreads();
            if (kc + 1 < NCHUNK) {
                if (kc + 1 >= 2) issueW(kc + 1, (kc + 1) & 1);
                issueA(kc + 1, (kc + 1) & 1);
                cp_commit();
            }

            #pragma unroll
            for (int kk = 0; kk < 16; ++kk) {
                const uint32_t acol = (((uint32_t)(2 * kk) + tA) ^ swz) << 4;
                const uint32_t bcol = (((uint32_t)(2 * kk) + tB) ^ swz) << 4;
                uint32_t a[2][4], bf[2][4];
                ldsm4(a[0], aBase[st][0] + acol);
                ldsm4(a[1], aBase[st][1] + acol);
                ldsm4(bf[0], bBase[st][0] + bcol);   // gates 0,1
                ldsm4(bf[1], bBase[st][1] + bcol);   // gates 2,3
                #pragma unroll
                for (int mi = 0; mi < 2; ++mi) {
                    mma16816(acc[mi][0], a[mi], bf[0][0], bf[0][1]);
                    mma16816(acc[mi][1], a[mi], bf[0][2], bf[0][3]);
                    mma16816(acc[mi][2], a[mi], bf[1][0], bf[1][1]);
                    mma16816(acc[mi][3], a[mi], bf[1][2], bf[1][3]);
                }
            }
        }

        // ---- cell math fully in registers (acc[mi][gate][q], q = rh*2 + e) ----
        __half* hout = g_h + ((size_t)slot * L_ + l) * (B_ * H_);
        #pragma unroll
        for (int mi = 0; mi < 2; ++mi)
            #pragma unroll
            for (int rh = 0; rh < 2; ++rh) {
                float hv2[2];
                #pragma unroll
                for (int e = 0; e < 2; ++e) {
                    const int q = rh * 2 + e;
                    float ai = acc[mi][0][q] + bias_r[0][e];
                    float af = acc[mi][1][q] + bias_r[1][e];
                    float ag = acc[mi][2][q] + bias_r[2][e];
                    float ao = acc[mi][3][q] + bias_r[3][e];
                    float ig = sig_fast(ai);
                    float fg = sig_fast(af);
                    float gg = tanh_fast(ag);
                    float og = sig_fast(ao);
                    float cs = fg * cst[mi][rh][e] + ig * gg;
                    cst[mi][rh][e] = cs;
                    hv2[e] = og * tanh_fast(cs);
                }
                int b = wm * 32 + mi * 16 + rh * 8 + grp;
                int go = b * 1024 + s * 32 + wn * 8 + tg * 2;
                __half2 hp = __floats2half2_rn(hv2[0], hv2[1]);
                __stcg((unsigned*)(hout + go), *(unsigned*)&hp);
                if (l == 3 && t == T_ - 1) {
                    g_h3[go]     = hv2[0];
                    g_h3[go + 1] = hv2[1];
                }
            }
        __syncthreads();                 // all h writes of this CTA issued

        if (tid == 0) {
            __threadfence();             // release: h visible before count
            atomicAdd(&g_done[l], 1u);
        }

        // next-step W prefetch (uncommitted) — overlaps the dataflow waits
        if (t + 1 < T_) { issueW(0, 0); issueW(1, 1); }
    }
}

// ---------------- final FC: out[b][o] = h3[b] . fc_w[o] + fc_b[o] ----------------
__global__ void fc_kernel(const float* __restrict__ fc_w,
                          const float* __restrict__ fc_b,
                          float* __restrict__ out) {
    __shared__ float hs[H_];
    const int b = blockIdx.x;
    const int o = threadIdx.x;
    for (int k = o; k < H_; k += O_) hs[k] = g_h3[b * H_ + k];
    __syncthreads();
    const float* w = fc_w + (long long)o * H_;
    float a0 = 0.f, a1 = 0.f, a2 = 0.f, a3 = 0.f;
    #pragma unroll 4
    for (int k = 0; k < H_; k += 4) {
        a0 += hs[k + 0] * __ldg(w + k + 0);
        a1 += hs[k + 1] * __ldg(w + k + 1);
        a2 += hs[k + 2] * __ldg(w + k + 2);
        a3 += hs[k + 3] * __ldg(w + k + 3);
    }
    out[b * O_ + o] = fc_b[o] + ((a0 + a1) + (a2 + a3));
}

// ---------------- launch ----------------------------------------------------------
extern "C" void kernel_launch(void* const* d_in, const int* in_sizes, int n_in,
                              void* d_out, int out_size) {
    (void)in_sizes; (void)n_in; (void)out_size;
    const float* x    = (const float*)d_in[0];
    const float* Wih  = (const float*)d_in[1];
    const float* Whh  = (const float*)d_in[2];
    const float* bih  = (const float*)d_in[3];
    const float* bhh  = (const float*)d_in[4];
    const float* fc_w = (const float*)d_in[5];
    const float* fc_b = (const float*)d_in[6];

    cudaFuncSetAttribute(lstm_kernel, cudaFuncAttributeMaxDynamicSharedMemorySize, SMEM_TOTAL);
    prep_kernel<<<2048, 256>>>(x, Wih, Whh, bih, bhh);
    lstm_kernel<<<NCTA, NTHR, SMEM_TOTAL>>>();
    fc_kernel<<<B_, O_>>>(fc_w, fc_b, (float*)d_out);
}